// round 5
// baseline (speedup 1.0000x reference)
#include <cuda_runtime.h>

#define B_  4
#define K_  16
#define H_  480
#define W_  640
#define HW_ (H_*W_)
#define P_  200000

#define EPS_T 1e-4f

// Pre-packed point-cloud features: one aligned 16B row per point -> one 32B
// L2 sector per gather.
__device__ float4 g_tab[P_];

__global__ void prep_kernel(const float* __restrict__ pt) {
    int i = blockIdx.x * blockDim.x + threadIdx.x;
    if (i < P_) {
        g_tab[i] = make_float4(pt[i], pt[P_ + i], pt[2 * P_ + i], 0.f);
    }
}

// 2 pixels per thread: pixel p and p+256 (coalescing preserved), doubling the
// number of independent gather LDGs in flight per thread.
__global__ void __launch_bounds__(256) composite_kernel(
    const int*   __restrict__ frag,   // int32
    const float* __restrict__ alpha,
    const float* __restrict__ im,
    float*       __restrict__ out)
{
    int t  = threadIdx.x;
    int p0 = blockIdx.x * 512 + t;          // first pixel
    int b  = blockIdx.y;
    size_t base0 = (size_t)b * K_ * HW_ + p0;

    float T[2]  = {1.f, 1.f};
    float c0[2] = {0.f, 0.f}, c1[2] = {0.f, 0.f}, c2[2] = {0.f, 0.f};
    bool  bg[2] = {false, false};

    #pragma unroll
    for (int half = 0; half < 2; half++) {
        int   f[2][8];
        float w[2][8];
        // Phase 1: 32 independent streaming LDGs (both pixels, 8 layers each).
        #pragma unroll
        for (int u = 0; u < 2; u++) {
            #pragma unroll
            for (int j = 0; j < 8; j++) {
                size_t off = base0 + (size_t)u * 256 + (size_t)(half * 8 + j) * HW_;
                f[u][j] = frag[off];
                w[u][j] = alpha[off];
            }
        }
        if (half == 0) { bg[0] = (f[0][0] < 0); bg[1] = (f[1][0] < 0); }

        // Phase 2: weight chains (pure FMA, data-predicated truncation).
        #pragma unroll
        for (int u = 0; u < 2; u++) {
            #pragma unroll
            for (int j = 0; j < 8; j++) {
                bool  v  = (f[u][j] >= 0);
                float av = v ? w[u][j] : 0.f;
                w[u][j] = (v && T[u] > EPS_T) ? av * T[u] : 0.f;
                T[u] *= (1.f - av);
            }
        }

        // Phase 3: up to 16 independent predicated gathers in flight.
        #pragma unroll
        for (int u = 0; u < 2; u++) {
            #pragma unroll
            for (int j = 0; j < 8; j++) {
                if (w[u][j] != 0.f) {
                    float4 ft = __ldg(&g_tab[f[u][j]]);
                    c0[u] = fmaf(w[u][j], ft.x, c0[u]);
                    c1[u] = fmaf(w[u][j], ft.y, c1[u]);
                    c2[u] = fmaf(w[u][j], ft.z, c2[u]);
                }
            }
        }

        // Phase 4: single mid-point ballot over both pixels.
        if (half == 0 &&
            !__any_sync(0xffffffffu, T[0] > EPS_T || T[1] > EPS_T)) break;
    }

    #pragma unroll
    for (int u = 0; u < 2; u++) {
        int p = p0 + u * 256;
        size_t ob = (size_t)b * 3 * HW_ + p;
        out[ob          ] = bg[u] ? im[p          ] : c0[u];
        out[ob +     HW_] = bg[u] ? im[p +     HW_] : c1[u];
        out[ob + 2 * HW_] = bg[u] ? im[p + 2 * HW_] : c2[u];
    }
}

extern "C" void kernel_launch(void* const* d_in, const int* in_sizes, int n_in,
                              void* d_out, int out_size) {
    const int*   frag  = (const int*)  d_in[0];
    const float* alpha = (const float*)d_in[1];
    const float* pt    = (const float*)d_in[2];
    const float* im    = (const float*)d_in[3];
    float*       out   = (float*)      d_out;

    prep_kernel<<<(P_ + 255) / 256, 256>>>(pt);

    dim3 grid(HW_ / 512, B_);   // 307200 % 512 == 0 -> 600 x 4 blocks
    composite_kernel<<<grid, 256>>>(frag, alpha, im, out);
}

// round 6
// speedup vs baseline: 1.9328x; 1.9328x over previous
#include <cuda_runtime.h>

#define B_  4
#define K_  16
#define H_  480
#define W_  640
#define HW_ (H_*W_)
#define P_  200000

// Truncation threshold on exclusive transmittance. Measured rel_err at 1e-4
// was 4.14e-5; linear scaling predicts ~2e-4 here (gate: 1e-3).
#define EPS_T 5e-4f

// Pre-packed point-cloud features: one aligned 16B row per point -> one 32B
// L2 sector per gather.
__device__ float4 g_tab[P_];

__global__ void prep_kernel(const float* __restrict__ pt) {
    int i = blockIdx.x * blockDim.x + threadIdx.x;
    if (i < P_) {
        g_tab[i] = make_float4(pt[i], pt[P_ + i], pt[2 * P_ + i], 0.f);
    }
}

__global__ void __launch_bounds__(256) composite_kernel(
    const int*   __restrict__ frag,   // int32 (JAX demotes int64 without x64 mode)
    const float* __restrict__ alpha,
    const float* __restrict__ im,
    float*       __restrict__ out)
{
    int p = blockIdx.x * blockDim.x + threadIdx.x;  // pixel within a batch image
    int b = blockIdx.y;
    size_t base = (size_t)b * K_ * HW_ + p;

    float T  = 1.f;
    float c0 = 0.f, c1 = 0.f, c2 = 0.f;
    bool  bg = false;

    #pragma unroll
    for (int half = 0; half < 2; half++) {
        // Batch-load 8 frags + 8 alphas (16 independent LDGs -> full MLP; no
        // control dependence between halves, so ptxas may hoist further).
        int   f[8];
        float w[8];
        #pragma unroll
        for (int j = 0; j < 8; j++) {
            size_t off = base + (size_t)(half * 8 + j) * HW_;
            f[j] = frag[off];
            w[j] = alpha[off];
        }
        if (half == 0) {
            bg = (f[0] < 0);
            if (bg) T = 0.f;   // background: zero every weight -> zero gathers
        }

        // Weight chain in pure FMA; data-predicated truncation.
        #pragma unroll
        for (int j = 0; j < 8; j++) {
            bool  v  = (f[j] >= 0);
            float av = v ? w[j] : 0.f;
            w[j] = (v && T > EPS_T) ? av * T : 0.f;   // exclusive-transmittance weight
            T *= (1.f - av);
        }

        // Predicated independent gathers (skip all zero-weight layers).
        #pragma unroll
        for (int j = 0; j < 8; j++) {
            if (w[j] != 0.f) {
                float4 ft = __ldg(&g_tab[f[j]]);
                c0 = fmaf(w[j], ft.x, c0);
                c1 = fmaf(w[j], ft.y, c1);
                c2 = fmaf(w[j], ft.z, c2);
            }
        }
    }

    size_t ob = (size_t)b * 3 * HW_ + p;
    out[ob          ] = bg ? im[p          ] : c0;
    out[ob +     HW_] = bg ? im[p +     HW_] : c1;
    out[ob + 2 * HW_] = bg ? im[p + 2 * HW_] : c2;
}

extern "C" void kernel_launch(void* const* d_in, const int* in_sizes, int n_in,
                              void* d_out, int out_size) {
    const int*   frag  = (const int*)  d_in[0];
    const float* alpha = (const float*)d_in[1];
    const float* pt    = (const float*)d_in[2];
    const float* im    = (const float*)d_in[3];
    float*       out   = (float*)      d_out;

    prep_kernel<<<(P_ + 255) / 256, 256>>>(pt);

    dim3 grid(HW_ / 256, B_);   // 1200 x 4 blocks
    composite_kernel<<<grid, 256>>>(frag, alpha, im, out);
}